// round 2
// baseline (speedup 1.0000x reference)
#include <cuda_runtime.h>
#include <math.h>

// Problem constants
#define TOK   4096         // B*N
#define CDIM  1024
#define HEADS 16
#define NBAT  4
#define NSEQ  1024
#define HD    64

// Scratch (device globals: allocation-free per harness rules)
__device__ float g_h[TOK * CDIM];                              // 16 MB  LN output
__device__ float g_qkv[TOK * 3 * CDIM];                        // 48 MB  qkv / cross q,k,v
__device__ float g_s[(size_t)NBAT * HEADS * NSEQ * NSEQ];      // 256 MB attention scores
__device__ float g_attn[TOK * CDIM];                           // 16 MB  attn concat output
__device__ float g_mlp[TOK * 4 * CDIM];                        // 64 MB  MLP hidden

// ---------------------------------------------------------------------------
// LayerNorm (no affine, eps=1e-6): one block (256 thr) per row of 1024
// ---------------------------------------------------------------------------
__global__ void ln_kernel(const float* __restrict__ in, float* __restrict__ out) {
    __shared__ float sred[256];
    int row = blockIdx.x;
    const float* p = in + (size_t)row * CDIM;
    float v[4];
    float s = 0.f;
#pragma unroll
    for (int i = 0; i < 4; i++) { v[i] = p[threadIdx.x + 256 * i]; s += v[i]; }
    sred[threadIdx.x] = s; __syncthreads();
    for (int o = 128; o > 0; o >>= 1) {
        if (threadIdx.x < o) sred[threadIdx.x] += sred[threadIdx.x + o];
        __syncthreads();
    }
    float mean = sred[0] * (1.f / CDIM);
    __syncthreads();
    float q = 0.f;
#pragma unroll
    for (int i = 0; i < 4; i++) { float d = v[i] - mean; q += d * d; }
    sred[threadIdx.x] = q; __syncthreads();
    for (int o = 128; o > 0; o >>= 1) {
        if (threadIdx.x < o) sred[threadIdx.x] += sred[threadIdx.x + o];
        __syncthreads();
    }
    float inv = rsqrtf(sred[0] * (1.f / CDIM) + 1e-6f);
    float* po = out + (size_t)row * CDIM;
#pragma unroll
    for (int i = 0; i < 4; i++) po[threadIdx.x + 256 * i] = (v[i] - mean) * inv;
}

// ---------------------------------------------------------------------------
// Masked softmax over rows of g_s. grid.x = B*H*N rows of length NSEQ.
// row -> head = row/NSEQ, b = head/HEADS. attn = s*scale + (mask? 0 : -1e4)
// ---------------------------------------------------------------------------
__global__ void softmax_kernel(float* __restrict__ S, const int* __restrict__ mask) {
    __shared__ float sred[256];
    size_t row = blockIdx.x;
    float* p = S + row * NSEQ;
    int head = blockIdx.x >> 10;       // row / 1024
    int b = head / HEADS;
    const int* mrow = mask + b * NSEQ;
    const float scale = 0.125f;        // 64^-0.5
    float v[4];
    float mx = -1e30f;
#pragma unroll
    for (int i = 0; i < 4; i++) {
        int k = threadIdx.x + 256 * i;
        float madd = (mrow[k] == 1) ? 0.f : -10000.f;
        v[i] = p[k] * scale + madd;
        mx = fmaxf(mx, v[i]);
    }
    sred[threadIdx.x] = mx; __syncthreads();
    for (int o = 128; o > 0; o >>= 1) {
        if (threadIdx.x < o) sred[threadIdx.x] = fmaxf(sred[threadIdx.x], sred[threadIdx.x + o]);
        __syncthreads();
    }
    mx = sred[0]; __syncthreads();
    float s = 0.f;
#pragma unroll
    for (int i = 0; i < 4; i++) { v[i] = expf(v[i] - mx); s += v[i]; }
    sred[threadIdx.x] = s; __syncthreads();
    for (int o = 128; o > 0; o >>= 1) {
        if (threadIdx.x < o) sred[threadIdx.x] += sred[threadIdx.x + o];
        __syncthreads();
    }
    float inv = 1.f / sred[0];
#pragma unroll
    for (int i = 0; i < 4; i++) p[threadIdx.x + 256 * i] = v[i] * inv;
}

// ---------------------------------------------------------------------------
// Tiled SGEMM. C[M,N] = A[M,K] @ (TB ? B[N,K]^T : B[K,N]) (+bias)(+GELU)(+res)
// Batched via blockIdx.z: z -> (b = z/Hdiv, h = z%Hdiv), base-pointer offsets
// A += b*sAb + h*sAh etc. All tile dims assumed to divide M/N/K exactly.
// ---------------------------------------------------------------------------
template <int BM, int BN, int BK, int TM, int TN, bool TB, bool GELU>
__global__ void __launch_bounds__((BM / TM) * (BN / TN))
sgemm_kernel(const float* __restrict__ A, const float* __restrict__ B,
             const float* __restrict__ bias, const float* __restrict__ res,
             float* __restrict__ C,
             int M, int N, int K, int lda, int ldb, int ldc,
             int Hdiv, long long sAb, long long sAh,
             long long sBb, long long sBh, long long sCb, long long sCh) {
    constexpr int NT = (BM / TM) * (BN / TN);
    int z = blockIdx.z;
    int bidx = z / Hdiv, hidx = z % Hdiv;
    A += bidx * sAb + hidx * sAh;
    B += bidx * sBb + hidx * sBh;
    C += bidx * sCb + hidx * sCh;
    if (res) res += bidx * sCb + hidx * sCh;

    __shared__ float As[BK][BM];
    __shared__ float Bs[BK][BN];

    int tid = threadIdx.x;
    constexpr int TCOLS = BN / TN;
    int trow = tid / TCOLS;
    int tcol = tid % TCOLS;

    int rowBase = blockIdx.y * BM;
    int colBase = blockIdx.x * BN;

    float acc[TM][TN];
#pragma unroll
    for (int i = 0; i < TM; i++)
#pragma unroll
        for (int j = 0; j < TN; j++) acc[i][j] = 0.f;

    for (int k0 = 0; k0 < K; k0 += BK) {
#pragma unroll
        for (int i = tid; i < BM * BK; i += NT) {
            int r = i / BK, c = i % BK;
            As[c][r] = A[(size_t)(rowBase + r) * lda + (k0 + c)];
        }
        if (TB) {
#pragma unroll
            for (int i = tid; i < BN * BK; i += NT) {
                int r = i / BK, c = i % BK;
                Bs[c][r] = B[(size_t)(colBase + r) * ldb + (k0 + c)];
            }
        } else {
#pragma unroll
            for (int i = tid; i < BK * BN; i += NT) {
                int r = i / BN, c = i % BN;
                Bs[r][c] = B[(size_t)(k0 + r) * ldb + (colBase + c)];
            }
        }
        __syncthreads();
#pragma unroll
        for (int kk = 0; kk < BK; kk++) {
            float a[TM], bb[TN];
#pragma unroll
            for (int i = 0; i < TM; i++) a[i] = As[kk][trow * TM + i];
#pragma unroll
            for (int j = 0; j < TN; j++) bb[j] = Bs[kk][tcol * TN + j];
#pragma unroll
            for (int i = 0; i < TM; i++)
#pragma unroll
                for (int j = 0; j < TN; j++) acc[i][j] += a[i] * bb[j];
        }
        __syncthreads();
    }

#pragma unroll
    for (int i = 0; i < TM; i++) {
        int gr = rowBase + trow * TM + i;
#pragma unroll
        for (int j = 0; j < TN; j++) {
            int gc = colBase + tcol * TN + j;
            float v = acc[i][j];
            if (bias) v += bias[gc];
            if (GELU) v = 0.5f * v * (1.f + erff(v * 0.70710678118654752f));
            if (res) v += res[(size_t)gr * ldc + gc];
            C[(size_t)gr * ldc + gc] = v;
        }
    }
}

// ---------------------------------------------------------------------------
// Host-side launch orchestration
// ---------------------------------------------------------------------------
extern "C" void kernel_launch(void* const* d_in, const int* in_sizes, int n_in,
                              void* d_out, int out_size) {
    const float* x_in     = (const float*)d_in[0];
    const float* c_in     = (const float*)d_in[1];
    const int*   mask     = (const int*)d_in[2];
    const float* sa_qkv_w = (const float*)d_in[3];
    const float* sa_qkv_b = (const float*)d_in[4];
    const float* sa_proj_w= (const float*)d_in[5];
    const float* sa_proj_b= (const float*)d_in[6];
    const float* ca_q_w   = (const float*)d_in[7];
    const float* ca_q_b   = (const float*)d_in[8];
    const float* ca_k_w   = (const float*)d_in[9];
    const float* ca_k_b   = (const float*)d_in[10];
    const float* ca_v_w   = (const float*)d_in[11];
    const float* ca_v_b   = (const float*)d_in[12];
    const float* ca_proj_w= (const float*)d_in[13];
    const float* ca_proj_b= (const float*)d_in[14];
    const float* fc1_w    = (const float*)d_in[15];
    const float* fc1_b    = (const float*)d_in[16];
    const float* fc2_w    = (const float*)d_in[17];
    const float* fc2_b    = (const float*)d_in[18];

    float* xb = (float*)d_out;  // running residual stream (also final output)

    float *gh, *gqkv, *gs, *gattn, *gmlp;
    cudaGetSymbolAddress((void**)&gh,    g_h);
    cudaGetSymbolAddress((void**)&gqkv,  g_qkv);
    cudaGetSymbolAddress((void**)&gs,    g_s);
    cudaGetSymbolAddress((void**)&gattn, g_attn);
    cudaGetSymbolAddress((void**)&gmlp,  g_mlp);

    const long long Z = 0;

    // x -> d_out (residual stream)
    cudaMemcpyAsync(xb, x_in, (size_t)TOK * CDIM * sizeof(float),
                    cudaMemcpyDeviceToDevice, 0);

    // ===================== self-attention =====================
    ln_kernel<<<TOK, 256>>>(xb, gh);

    // qkv = ln(x) @ sa_qkv_w + b : [4096,1024]x[1024,3072]
    sgemm_kernel<128,128,8,8,8,false,false><<<dim3(3072/128, TOK/128, 1), 256>>>(
        gh, sa_qkv_w, sa_qkv_b, nullptr, gqkv,
        TOK, 3*CDIM, CDIM, CDIM, 3*CDIM, 3*CDIM, 1, Z,Z,Z,Z,Z,Z);

    // S = Q K^T  (batched over 64 = B*H)
    {
        long long sAb = (long long)NSEQ * 3 * CDIM, sAh = HD;
        long long sCb = (long long)HEADS * NSEQ * NSEQ, sCh = (long long)NSEQ * NSEQ;
        sgemm_kernel<128,128,8,8,8,true,false><<<dim3(NSEQ/128, NSEQ/128, NBAT*HEADS), 256>>>(
            gqkv /*Q*/, gqkv + CDIM /*K*/, nullptr, nullptr, gs,
            NSEQ, NSEQ, HD, 3*CDIM, 3*CDIM, NSEQ,
            HEADS, sAb, sAh, sAb, sAh, sCb, sCh);
    }

    softmax_kernel<<<NBAT*HEADS*NSEQ, 256>>>(gs, mask);

    // attn = P @ V -> g_attn[b][n][h*64+d]
    {
        long long sPb = (long long)HEADS * NSEQ * NSEQ, sPh = (long long)NSEQ * NSEQ;
        long long sVb = (long long)NSEQ * 3 * CDIM, sVh = HD;
        long long sCb = (long long)NSEQ * CDIM, sCh = HD;
        sgemm_kernel<128,64,8,8,4,false,false><<<dim3(1, NSEQ/128, NBAT*HEADS), 256>>>(
            gs, gqkv + 2*CDIM /*V*/, nullptr, nullptr, gattn,
            NSEQ, HD, NSEQ, NSEQ, 3*CDIM, CDIM,
            HEADS, sPb, sPh, sVb, sVh, sCb, sCh);
    }

    // x += attn @ sa_proj_w + b
    sgemm_kernel<128,128,8,8,8,false,false><<<dim3(CDIM/128, TOK/128, 1), 256>>>(
        gattn, sa_proj_w, sa_proj_b, xb, xb,
        TOK, CDIM, CDIM, CDIM, CDIM, CDIM, 1, Z,Z,Z,Z,Z,Z);

    // ===================== cross-attention =====================
    ln_kernel<<<TOK, 256>>>(xb, gh);

    float* gq = gqkv;
    float* gk = gqkv + (size_t)TOK * CDIM;
    float* gv = gqkv + (size_t)2 * TOK * CDIM;

    sgemm_kernel<128,128,8,8,8,false,false><<<dim3(CDIM/128, TOK/128, 1), 256>>>(
        gh, ca_q_w, ca_q_b, nullptr, gq,
        TOK, CDIM, CDIM, CDIM, CDIM, CDIM, 1, Z,Z,Z,Z,Z,Z);
    sgemm_kernel<128,128,8,8,8,false,false><<<dim3(CDIM/128, TOK/128, 1), 256>>>(
        c_in, ca_k_w, ca_k_b, nullptr, gk,
        TOK, CDIM, CDIM, CDIM, CDIM, CDIM, 1, Z,Z,Z,Z,Z,Z);
    sgemm_kernel<128,128,8,8,8,false,false><<<dim3(CDIM/128, TOK/128, 1), 256>>>(
        c_in, ca_v_w, ca_v_b, nullptr, gv,
        TOK, CDIM, CDIM, CDIM, CDIM, CDIM, 1, Z,Z,Z,Z,Z,Z);

    {
        long long sAb = (long long)NSEQ * CDIM, sAh = HD;
        long long sCb = (long long)HEADS * NSEQ * NSEQ, sCh = (long long)NSEQ * NSEQ;
        sgemm_kernel<128,128,8,8,8,true,false><<<dim3(NSEQ/128, NSEQ/128, NBAT*HEADS), 256>>>(
            gq, gk, nullptr, nullptr, gs,
            NSEQ, NSEQ, HD, CDIM, CDIM, NSEQ,
            HEADS, sAb, sAh, sAb, sAh, sCb, sCh);
    }

    softmax_kernel<<<NBAT*HEADS*NSEQ, 256>>>(gs, mask);

    {
        long long sPb = (long long)HEADS * NSEQ * NSEQ, sPh = (long long)NSEQ * NSEQ;
        long long sVb = (long long)NSEQ * CDIM, sVh = HD;
        long long sCb = (long long)NSEQ * CDIM, sCh = HD;
        sgemm_kernel<128,64,8,8,4,false,false><<<dim3(1, NSEQ/128, NBAT*HEADS), 256>>>(
            gs, gv, nullptr, nullptr, gattn,
            NSEQ, HD, NSEQ, NSEQ, CDIM, CDIM,
            HEADS, sPb, sPh, sVb, sVh, sCb, sCh);
    }

    sgemm_kernel<128,128,8,8,8,false,false><<<dim3(CDIM/128, TOK/128, 1), 256>>>(
        gattn, ca_proj_w, ca_proj_b, xb, xb,
        TOK, CDIM, CDIM, CDIM, CDIM, CDIM, 1, Z,Z,Z,Z,Z,Z);

    // ===================== MLP =====================
    ln_kernel<<<TOK, 256>>>(xb, gh);

    // h = gelu(ln(x) @ fc1_w + b) : [4096,1024]x[1024,4096]
    sgemm_kernel<128,128,8,8,8,false,true><<<dim3(4*CDIM/128, TOK/128, 1), 256>>>(
        gh, fc1_w, fc1_b, nullptr, gmlp,
        TOK, 4*CDIM, CDIM, CDIM, 4*CDIM, 4*CDIM, 1, Z,Z,Z,Z,Z,Z);

    // x += h @ fc2_w + b : [4096,4096]x[4096,1024]
    sgemm_kernel<128,128,8,8,8,false,false><<<dim3(CDIM/128, TOK/128, 1), 256>>>(
        gmlp, fc2_w, fc2_b, xb, xb,
        TOK, CDIM, 4*CDIM, 4*CDIM, CDIM, CDIM, 1, Z,Z,Z,Z,Z,Z);
}

// round 4
// speedup vs baseline: 3.5396x; 3.5396x over previous
#include <cuda_runtime.h>
#include <math.h>
#include <stdint.h>

// Problem constants
#define TOK   4096         // B*N
#define CDIM  1024
#define HEADS 16
#define NBAT  4
#define NSEQ  1024
#define HD    64

// Scratch (device globals: allocation-free per harness rules)
__device__ __align__(256) float g_h[TOK * CDIM];                              // 16 MB
__device__ __align__(256) float g_qkv[TOK * 3 * CDIM];                        // 48 MB
__device__ __align__(256) float g_s[(size_t)NBAT * HEADS * NSEQ * NSEQ];      // 256 MB
__device__ __align__(256) float g_attn[TOK * CDIM];                           // 16 MB
__device__ __align__(256) float g_mlp[TOK * 4 * CDIM];                        // 64 MB (also rounded-c)
__device__ __align__(256) float g_wt[4 * 1024 * 1024];                        // 16 MB (transposed weights)
__device__ __align__(256) float g_vt[(size_t)NBAT * HEADS * HD * NSEQ];       // 16 MB (transposed V)

// ---------------------------------------------------------------------------
// Helpers
// ---------------------------------------------------------------------------
__device__ __forceinline__ uint32_t smem_u32(const void* p) {
    uint32_t a;
    asm("{ .reg .u64 t; cvta.to.shared.u64 t, %1; cvt.u32.u64 %0, t; }" : "=r"(a) : "l"(p));
    return a;
}
__device__ __forceinline__ float rnd_tf32(float x) {
    uint32_t u;
    asm("cvt.rna.tf32.f32 %0, %1;" : "=r"(u) : "f"(x));
    return __uint_as_float(u);
}
#define CP_ASYNC16(dst, src) \
    asm volatile("cp.async.cg.shared.global [%0], [%1], 16;" :: "r"(dst), "l"(src) : "memory")
#define CP_COMMIT()  asm volatile("cp.async.commit_group;" ::: "memory")

__device__ __forceinline__ void mma8(float* d, const uint32_t* a, const uint32_t* b) {
    asm volatile("mma.sync.aligned.m16n8k8.row.col.f32.tf32.tf32.f32 "
                 "{%0,%1,%2,%3}, {%4,%5,%6,%7}, {%8,%9}, {%0,%1,%2,%3};"
                 : "+f"(d[0]), "+f"(d[1]), "+f"(d[2]), "+f"(d[3])
                 : "r"(a[0]), "r"(a[1]), "r"(a[2]), "r"(a[3]), "r"(b[0]), "r"(b[1]));
}

// ---------------------------------------------------------------------------
// LayerNorm (no affine, eps=1e-6), rounds output to tf32 (it feeds MMA only)
// ---------------------------------------------------------------------------
__global__ void ln_kernel(const float* __restrict__ in, float* __restrict__ out) {
    __shared__ float sred[256];
    int row = blockIdx.x;
    const float4* p = (const float4*)(in + (size_t)row * CDIM);
    float4 v = p[threadIdx.x];
    float s = v.x + v.y + v.z + v.w;
    sred[threadIdx.x] = s; __syncthreads();
    for (int o = 128; o > 0; o >>= 1) {
        if (threadIdx.x < o) sred[threadIdx.x] += sred[threadIdx.x + o];
        __syncthreads();
    }
    float mean = sred[0] * (1.f / CDIM);
    __syncthreads();
    float dx = v.x-mean, dy = v.y-mean, dz = v.z-mean, dw = v.w-mean;
    sred[threadIdx.x] = dx*dx + dy*dy + dz*dz + dw*dw; __syncthreads();
    for (int o = 128; o > 0; o >>= 1) {
        if (threadIdx.x < o) sred[threadIdx.x] += sred[threadIdx.x + o];
        __syncthreads();
    }
    float inv = rsqrtf(sred[0] * (1.f / CDIM) + 1e-6f);
    float4 r = make_float4(rnd_tf32(dx*inv), rnd_tf32(dy*inv),
                           rnd_tf32(dz*inv), rnd_tf32(dw*inv));
    ((float4*)(out + (size_t)row * CDIM))[threadIdx.x] = r;
}

// ---------------------------------------------------------------------------
// Masked softmax; output rounded to tf32 (feeds PV MMA)
// ---------------------------------------------------------------------------
__global__ void softmax_kernel(float* __restrict__ S, const int* __restrict__ mask) {
    __shared__ float sred[256];
    size_t row = blockIdx.x;
    float4* p = (float4*)(S + row * NSEQ);
    int b = blockIdx.x >> 14;
    const int4* mrow = (const int4*)(mask + b * NSEQ);
    const float scale = 0.125f;
    float4 v = p[threadIdx.x];
    int4 m = mrow[threadIdx.x];
    v.x = v.x * scale + ((m.x == 1) ? 0.f : -10000.f);
    v.y = v.y * scale + ((m.y == 1) ? 0.f : -10000.f);
    v.z = v.z * scale + ((m.z == 1) ? 0.f : -10000.f);
    v.w = v.w * scale + ((m.w == 1) ? 0.f : -10000.f);
    float mx = fmaxf(fmaxf(v.x, v.y), fmaxf(v.z, v.w));
    sred[threadIdx.x] = mx; __syncthreads();
    for (int o = 128; o > 0; o >>= 1) {
        if (threadIdx.x < o) sred[threadIdx.x] = fmaxf(sred[threadIdx.x], sred[threadIdx.x + o]);
        __syncthreads();
    }
    mx = sred[0]; __syncthreads();
    v.x = __expf(v.x - mx); v.y = __expf(v.y - mx);
    v.z = __expf(v.z - mx); v.w = __expf(v.w - mx);
    sred[threadIdx.x] = v.x + v.y + v.z + v.w; __syncthreads();
    for (int o = 128; o > 0; o >>= 1) {
        if (threadIdx.x < o) sred[threadIdx.x] += sred[threadIdx.x + o];
        __syncthreads();
    }
    float inv = 1.f / sred[0];
    v.x = rnd_tf32(v.x * inv); v.y = rnd_tf32(v.y * inv);
    v.z = rnd_tf32(v.z * inv); v.w = rnd_tf32(v.w * inv);
    p[threadIdx.x] = v;
}

// ---------------------------------------------------------------------------
// Elementwise round-to-tf32 copy (for raw c input feeding K/V GEMMs)
// ---------------------------------------------------------------------------
__global__ void round_copy(const float* __restrict__ in, float* __restrict__ out) {
    size_t i = (size_t)blockIdx.x * 256 + threadIdx.x;
    float4 v = ((const float4*)in)[i];
    v.x = rnd_tf32(v.x); v.y = rnd_tf32(v.y);
    v.z = rnd_tf32(v.z); v.w = rnd_tf32(v.w);
    ((float4*)out)[i] = v;
}

// ---------------------------------------------------------------------------
// Batched 32x32 tiled transpose, output rounded to tf32 (feeds MMA B operand)
// ---------------------------------------------------------------------------
__global__ void transpose_kernel(const float* __restrict__ in, float* __restrict__ out,
                                 int ldin, int ldout, int Hdiv,
                                 long long sInB, long long sInH,
                                 long long sOutB, long long sOutH) {
    __shared__ float t[32][33];
    int z = blockIdx.z;
    int zb = z / Hdiv, zh = z % Hdiv;
    in  += zb * sInB + zh * sInH;
    out += zb * sOutB + zh * sOutH;
    int c0 = blockIdx.x * 32, r0 = blockIdx.y * 32;
    int x = threadIdx.x, y = threadIdx.y;
#pragma unroll
    for (int i = 0; i < 32; i += 8)
        t[y + i][x] = in[(size_t)(r0 + y + i) * ldin + c0 + x];
    __syncthreads();
#pragma unroll
    for (int i = 0; i < 32; i += 8)
        out[(size_t)(c0 + y + i) * ldout + r0 + x] = rnd_tf32(t[x][y + i]);
}

// ---------------------------------------------------------------------------
// tf32 mma.sync GEMM. C[M,N] = A[M,K] @ B[N,K]^T (+bias)(+GELU)(+res)(+round)
// BM=128, BK=32, 256 thr, 8 warps (2x4), warp tile 64 x (BN/4).
// A,B K-major; double-buffered cp.async. Batched via blockIdx.z.
// mode: bit0 = GELU, bit1 = round output to tf32.
// ---------------------------------------------------------------------------
template <int BN>
__global__ void __launch_bounds__(256, 2)
mm_mma(const float* __restrict__ A, const float* __restrict__ B,
       const float* __restrict__ bias, const float* __restrict__ res,
       float* __restrict__ C, int K, int lda, int ldb, int ldc, int mode,
       int Hdiv, long long sAb, long long sAh, long long sBb, long long sBh,
       long long sCb, long long sCh) {
    constexpr int BM = 128, BK = 32, AST = BK + 4;    // padded stride (floats)
    constexpr int ABYTES = BM * AST * 4;               // 18432
    constexpr int BBYTES = BN * AST * 4;
    constexpr int WN = BN / 4;                         // 32 or 16
    constexpr int NT = WN / 8;                         // 4 or 2
    constexpr int MT = 4;                              // 64/16

    extern __shared__ char smem[];
    uint32_t sb = smem_u32(smem);
    uint32_t sA[2] = { sb, sb + ABYTES };
    uint32_t sB[2] = { sb + 2 * ABYTES, sb + 2 * ABYTES + BBYTES };

    int tid = threadIdx.x;
    int wid = tid >> 5, lane = tid & 31;
    int warpM = wid >> 2, warpN = wid & 3;
    int lr = lane >> 2, lc = lane & 3;

    int z = blockIdx.z;
    int bb = z / Hdiv, hh = z % Hdiv;
    A += bb * sAb + hh * sAh;
    B += bb * sBb + hh * sBh;
    long long cOff = bb * sCb + hh * sCh;
    C += cOff;
    if (res) res += cOff;

    int rowBase = blockIdx.y * BM;
    int colBase = blockIdx.x * BN;

    float acc[MT][NT][4];
#pragma unroll
    for (int i = 0; i < MT; i++)
#pragma unroll
        for (int j = 0; j < NT; j++)
#pragma unroll
            for (int q = 0; q < 4; q++) acc[i][j][q] = 0.f;

    auto load_stage = [&](int buf, int k0) {
#pragma unroll
        for (int i = 0; i < (BM * 8) / 256; i++) {     // 4
            int idx = tid + i * 256;
            int row = idx >> 3, c = idx & 7;
            uint32_t dst = sA[buf] + (uint32_t)(row * (AST * 4) + c * 16);
            const float* src = A + (size_t)(rowBase + row) * lda + k0 + c * 4;
            CP_ASYNC16(dst, src);
        }
#pragma unroll
        for (int i = 0; i < (BN * 8) / 256; i++) {     // 4 or 2
            int idx = tid + i * 256;
            int row = idx >> 3, c = idx & 7;
            uint32_t dst = sB[buf] + (uint32_t)(row * (AST * 4) + c * 16);
            const float* src = B + (size_t)(colBase + row) * ldb + k0 + c * 4;
            CP_ASYNC16(dst, src);
        }
        CP_COMMIT();
    };

    int nsteps = K / BK;
    load_stage(0, 0);
    load_stage(1, BK);

    for (int s = 0; s < nsteps; s++) {
        int buf = s & 1;
        if (s + 1 < nsteps) asm volatile("cp.async.wait_group 1;" ::: "memory");
        else                asm volatile("cp.async.wait_group 0;" ::: "memory");
        __syncthreads();

        const uint32_t* As = (const uint32_t*)(smem + (sA[buf] - sb));
        const uint32_t* Bs = (const uint32_t*)(smem + (sB[buf] - sb));
#pragma unroll
        for (int kk = 0; kk < BK; kk += 8) {
            uint32_t af[MT][4], bf[NT][2];
#pragma unroll
            for (int i = 0; i < MT; i++) {
                int m0 = warpM * 64 + i * 16 + lr;
                int k = kk + lc;
                af[i][0] = As[m0 * AST + k];
                af[i][1] = As[(m0 + 8) * AST + k];
                af[i][2] = As[m0 * AST + k + 4];
                af[i][3] = As[(m0 + 8) * AST + k + 4];
            }
#pragma unroll
            for (int j = 0; j < NT; j++) {
                int n0 = warpN * WN + j * 8 + lr;
                int k = kk + lc;
                bf[j][0] = Bs[n0 * AST + k];
                bf[j][1] = Bs[n0 * AST + k + 4];
            }
#pragma unroll
            for (int i = 0; i < MT; i++)
#pragma unroll
                for (int j = 0; j < NT; j++)
                    mma8(acc[i][j], af[i], bf[j]);
        }
        __syncthreads();
        if (s + 2 < nsteps) load_stage(buf, (s + 2) * BK);
    }

    // Epilogue
    bool gelu = mode & 1, rnd = mode & 2;
#pragma unroll
    for (int i = 0; i < MT; i++) {
#pragma unroll
        for (int j = 0; j < NT; j++) {
#pragma unroll
            for (int h = 0; h < 2; h++) {
                int r = rowBase + warpM * 64 + i * 16 + lr + h * 8;
                int cb = colBase + warpN * WN + j * 8 + lc * 2;
                float v0 = acc[i][j][h * 2 + 0];
                float v1 = acc[i][j][h * 2 + 1];
                if (bias) { v0 += bias[cb]; v1 += bias[cb + 1]; }
                if (gelu) {
                    v0 = 0.5f * v0 * (1.f + erff(v0 * 0.70710678118654752f));
                    v1 = 0.5f * v1 * (1.f + erff(v1 * 0.70710678118654752f));
                }
                if (rnd) { v0 = rnd_tf32(v0); v1 = rnd_tf32(v1); }
                size_t o = (size_t)r * ldc + cb;
                if (res) {
                    float2 rv = *(const float2*)(res + o);
                    v0 += rv.x; v1 += rv.y;
                }
                float2 out = make_float2(v0, v1);
                *(float2*)(C + o) = out;
            }
        }
    }
}

// ---------------------------------------------------------------------------
// Host-side launch orchestration
// ---------------------------------------------------------------------------
extern "C" void kernel_launch(void* const* d_in, const int* in_sizes, int n_in,
                              void* d_out, int out_size) {
    const float* x_in     = (const float*)d_in[0];
    const float* c_in     = (const float*)d_in[1];
    const int*   mask     = (const int*)d_in[2];
    const float* sa_qkv_w = (const float*)d_in[3];
    const float* sa_qkv_b = (const float*)d_in[4];
    const float* sa_proj_w= (const float*)d_in[5];
    const float* sa_proj_b= (const float*)d_in[6];
    const float* ca_q_w   = (const float*)d_in[7];
    const float* ca_q_b   = (const float*)d_in[8];
    const float* ca_k_w   = (const float*)d_in[9];
    const float* ca_k_b   = (const float*)d_in[10];
    const float* ca_v_w   = (const float*)d_in[11];
    const float* ca_v_b   = (const float*)d_in[12];
    const float* ca_proj_w= (const float*)d_in[13];
    const float* ca_proj_b= (const float*)d_in[14];
    const float* fc1_w    = (const float*)d_in[15];
    const float* fc1_b    = (const float*)d_in[16];
    const float* fc2_w    = (const float*)d_in[17];
    const float* fc2_b    = (const float*)d_in[18];

    float* xb = (float*)d_out;

    float *gh, *gqkv, *gs, *gattn, *gmlp, *gwt, *gvt;
    cudaGetSymbolAddress((void**)&gh,    g_h);
    cudaGetSymbolAddress((void**)&gqkv,  g_qkv);
    cudaGetSymbolAddress((void**)&gs,    g_s);
    cudaGetSymbolAddress((void**)&gattn, g_attn);
    cudaGetSymbolAddress((void**)&gmlp,  g_mlp);
    cudaGetSymbolAddress((void**)&gwt,   g_wt);
    cudaGetSymbolAddress((void**)&gvt,   g_vt);

    const int AST4 = (32 + 4) * 4;
    const int SMEM128 = 2 * 128 * AST4 + 2 * 128 * AST4;  // 73728
    const int SMEM64  = 2 * 128 * AST4 + 2 * 64  * AST4;  // 55296
    cudaFuncSetAttribute(mm_mma<128>, cudaFuncAttributeMaxDynamicSharedMemorySize, SMEM128);
    cudaFuncSetAttribute(mm_mma<64>,  cudaFuncAttributeMaxDynamicSharedMemorySize, SMEM64);

    const long long Z = 0;
    dim3 tblock(32, 8);

    cudaMemcpyAsync(xb, x_in, (size_t)TOK * CDIM * sizeof(float),
                    cudaMemcpyDeviceToDevice, 0);

    // ===================== self-attention =====================
    ln_kernel<<<TOK, 256>>>(xb, gh);

    transpose_kernel<<<dim3(3072/32, 1024/32, 1), tblock>>>(sa_qkv_w, gwt, 3072, 1024, 1, Z,Z,Z,Z);
    mm_mma<128><<<dim3(3072/128, TOK/128, 1), 256, SMEM128>>>(
        gh, gwt, sa_qkv_b, nullptr, gqkv, 1024, 1024, 1024, 3072, 2,
        1, Z,Z,Z,Z,Z,Z);

    // S = Q K^T  (batched over B*H)
    mm_mma<128><<<dim3(NSEQ/128, NSEQ/128, NBAT*HEADS), 256, SMEM128>>>(
        gqkv, gqkv + CDIM, nullptr, nullptr, gs, HD, 3072, 3072, NSEQ, 0,
        HEADS, (long long)NSEQ*3*CDIM, HD, (long long)NSEQ*3*CDIM, HD,
        (long long)HEADS*NSEQ*NSEQ, (long long)NSEQ*NSEQ);

    softmax_kernel<<<NBAT*HEADS*NSEQ, 256>>>(gs, mask);

    // Vt: [b,h,d,seq]
    transpose_kernel<<<dim3(HD/32, NSEQ/32, NBAT*HEADS), tblock>>>(
        gqkv + 2*CDIM, gvt, 3072, NSEQ, HEADS,
        (long long)NSEQ*3*CDIM, HD, (long long)HEADS*HD*NSEQ, (long long)HD*NSEQ);

    // attn = P @ V
    mm_mma<64><<<dim3(1, NSEQ/128, NBAT*HEADS), 256, SMEM64>>>(
        gs, gvt, nullptr, nullptr, gattn, NSEQ, NSEQ, NSEQ, CDIM, 2,
        HEADS, (long long)HEADS*NSEQ*NSEQ, (long long)NSEQ*NSEQ,
        (long long)HEADS*HD*NSEQ, (long long)HD*NSEQ,
        (long long)NSEQ*CDIM, HD);

    // x += attn @ sa_proj_w + b
    transpose_kernel<<<dim3(1024/32, 1024/32, 1), tblock>>>(sa_proj_w, gwt, 1024, 1024, 1, Z,Z,Z,Z);
    mm_mma<128><<<dim3(CDIM/128, TOK/128, 1), 256, SMEM128>>>(
        gattn, gwt, sa_proj_b, xb, xb, 1024, 1024, 1024, 1024, 0,
        1, Z,Z,Z,Z,Z,Z);

    // ===================== cross-attention =====================
    ln_kernel<<<TOK, 256>>>(xb, gh);

    float* gq = gqkv;
    float* gk = gqkv + (size_t)TOK * CDIM;
    float* gv = gqkv + (size_t)2 * TOK * CDIM;
    float* gcr = gmlp;   // gmlp is free until the MLP phase: rounded copy of c

    round_copy<<<TOK * CDIM / 4 / 256, 256>>>(c_in, gcr);

    transpose_kernel<<<dim3(1024/32, 1024/32, 1), tblock>>>(ca_q_w, gwt, 1024, 1024, 1, Z,Z,Z,Z);
    mm_mma<128><<<dim3(CDIM/128, TOK/128, 1), 256, SMEM128>>>(
        gh, gwt, ca_q_b, nullptr, gq, 1024, 1024, 1024, 1024, 2, 1, Z,Z,Z,Z,Z,Z);
    transpose_kernel<<<dim3(1024/32, 1024/32, 1), tblock>>>(ca_k_w, gwt, 1024, 1024, 1, Z,Z,Z,Z);
    mm_mma<128><<<dim3(CDIM/128, TOK/128, 1), 256, SMEM128>>>(
        gcr, gwt, ca_k_b, nullptr, gk, 1024, 1024, 1024, 1024, 2, 1, Z,Z,Z,Z,Z,Z);
    transpose_kernel<<<dim3(1024/32, 1024/32, 1), tblock>>>(ca_v_w, gwt, 1024, 1024, 1, Z,Z,Z,Z);
    mm_mma<128><<<dim3(CDIM/128, TOK/128, 1), 256, SMEM128>>>(
        gcr, gwt, ca_v_b, nullptr, gv, 1024, 1024, 1024, 1024, 2, 1, Z,Z,Z,Z,Z,Z);

    mm_mma<128><<<dim3(NSEQ/128, NSEQ/128, NBAT*HEADS), 256, SMEM128>>>(
        gq, gk, nullptr, nullptr, gs, HD, 1024, 1024, NSEQ, 0,
        HEADS, (long long)NSEQ*CDIM, HD, (long long)NSEQ*CDIM, HD,
        (long long)HEADS*NSEQ*NSEQ, (long long)NSEQ*NSEQ);

    softmax_kernel<<<NBAT*HEADS*NSEQ, 256>>>(gs, mask);

    transpose_kernel<<<dim3(HD/32, NSEQ/32, NBAT*HEADS), tblock>>>(
        gv, gvt, 1024, NSEQ, HEADS,
        (long long)NSEQ*CDIM, HD, (long long)HEADS*HD*NSEQ, (long long)HD*NSEQ);

    mm_mma<64><<<dim3(1, NSEQ/128, NBAT*HEADS), 256, SMEM64>>>(
        gs, gvt, nullptr, nullptr, gattn, NSEQ, NSEQ, NSEQ, CDIM, 2,
        HEADS, (long long)HEADS*NSEQ*NSEQ, (long long)NSEQ*NSEQ,
        (long long)HEADS*HD*NSEQ, (long long)HD*NSEQ,
        (long long)NSEQ*CDIM, HD);

    transpose_kernel<<<dim3(1024/32, 1024/32, 1), tblock>>>(ca_proj_w, gwt, 1024, 1024, 1, Z,Z,Z,Z);
    mm_mma<128><<<dim3(CDIM/128, TOK/128, 1), 256, SMEM128>>>(
        gattn, gwt, ca_proj_b, xb, xb, 1024, 1024, 1024, 1024, 0, 1, Z,Z,Z,Z,Z,Z);

    // ===================== MLP =====================
    ln_kernel<<<TOK, 256>>>(xb, gh);

    transpose_kernel<<<dim3(4096/32, 1024/32, 1), tblock>>>(fc1_w, gwt, 4096, 1024, 1, Z,Z,Z,Z);
    mm_mma<128><<<dim3(4096/128, TOK/128, 1), 256, SMEM128>>>(
        gh, gwt, fc1_b, nullptr, gmlp, 1024, 1024, 1024, 4096, 3, 1, Z,Z,Z,Z,Z,Z);

    transpose_kernel<<<dim3(1024/32, 4096/32, 1), tblock>>>(fc2_w, gwt, 1024, 4096, 1, Z,Z,Z,Z);
    mm_mma<128><<<dim3(CDIM/128, TOK/128, 1), 256, SMEM128>>>(
        gmlp, gwt, fc2_b, xb, xb, 4096, 4096, 4096, 1024, 0, 1, Z,Z,Z,Z,Z,Z);
}